// round 17
// baseline (speedup 1.0000x reference)
#include <cuda_runtime.h>
#include <cuda_fp16.h>

#define BB    8
#define PP    16384
#define KN    16
#define CK    144
#define IMG   (16*128*128)    // 262144 = 2^18
#define NT    128
#define NPX   2

#define W0STR 148             // px0 k-row stride (floats): 20*kp mod 32 full mult-of-4 set
#define W1STR 156             // px1 k-row stride (holds 144+12 replicated cols)
#define W0SZ  (KN*W0STR*4)    // 9472 B
#define W1SZ  (KN*W1STR*4)    // 9984 B
#define WSMB  (W0SZ + W1SZ)   // 19456 B
#define P0B   4672            // px0 patch bytes (144 rows used)
#define P1B   4896            // px1 patch bytes (153 rows: 144 + 9 replicas)
#define PATCHB (P0B + P1B)    // 9568 B
#define SMEM_BYTES (WSMB + PATCHB + 8)   // 29032
#define WBYTES (16*576 + 16*576 + 16*48) // 19200 TMA bytes

// 4 MB scratch: x transposed + fp16-packed, batch-innermost (row = 16B)
__device__ __align__(16) __half g_xth[IMG * BB];
__device__ int g_idx_is64;

__device__ __forceinline__ void fma2(unsigned long long& d,
                                     unsigned long long a, unsigned long long b) {
    asm("fma.rn.f32x2 %0, %1, %2, %0;" : "+l"(d) : "l"(a), "l"(b));
}

__device__ __forceinline__ void bulk_cp(unsigned dst, const void* src,
                                        unsigned bytes, unsigned mbar) {
    asm volatile(
        "{\n\t"
        ".reg .b64 pol;\n\t"
        "createpolicy.fractional.L2::evict_first.b64 pol, 1.0;\n\t"
        "cp.async.bulk.shared::cluster.global.mbarrier::complete_tx::bytes.L2::cache_hint"
        " [%0], [%1], %2, [%3], pol;\n\t"
        "}\n"
        :: "r"(dst), "l"(src), "r"(bytes), "r"(mbar) : "memory");
}

// Transpose+pack x [B][IMG] -> g_xth [IMG][B]; block 0 probes idx dtype.
__global__ __launch_bounds__(256) void transpose_kernel(
    const float* __restrict__ x, const unsigned* __restrict__ h32)
{
    if (blockIdx.x == 0 && threadIdx.x < 32) {
        unsigned v = h32[2u * (threadIdx.x * 36000u) + 1u];
        int all0 = __all_sync(0xFFFFFFFFu, v == 0u);
        if (threadIdx.x == 0) g_idx_is64 = all0;
    }
    int i = blockIdx.x * 256 + threadIdx.x;
    __half2 h[4];
    #pragma unroll
    for (int q = 0; q < 4; q++) {
        float lo = __ldg(&x[(2 * q) * IMG + i]);
        float hi = __ldg(&x[(2 * q + 1) * IMG + i]);
        h[q] = __floats2half2_rn(lo, hi);
    }
    *(uint4*)&g_xth[(size_t)i * BB] = *(uint4*)h;
}

// convert 8 halves -> 8 floats (two float4)
__device__ __forceinline__ void cvt8(uint4 h, float4& a, float4& b) {
    const __half2* ph = (const __half2*)&h;
    float2 f0 = __half22float2(ph[0]);
    float2 f1 = __half22float2(ph[1]);
    float2 f2 = __half22float2(ph[2]);
    float2 f3 = __half22float2(ph[3]);
    a = make_float4(f0.x, f0.y, f1.x, f1.y);
    b = make_float4(f2.x, f2.y, f3.x, f3.y);
}

__global__ __launch_bounds__(NT, 8) void abc2d_kernel(
    const float* __restrict__ weights,
    const unsigned* __restrict__ hidx32,
    float* __restrict__ out)
{
    extern __shared__ __align__(16) float smem[];
    char* patchb = (char*)smem + WSMB;                  // px0 then px1 fp32 rows (32B)
    unsigned mbar = (unsigned)__cvta_generic_to_shared(patchb + PATCHB);

    const int p0 = blockIdx.x * NPX;
    const int t  = threadIdx.x;
    const int is64 = g_idx_is64;

    if (t == 0) {
        asm volatile("mbarrier.init.shared.b64 [%0], 1;" :: "r"(mbar) : "memory");
        asm volatile("mbarrier.arrive.expect_tx.shared.b64 _, [%0], %1;"
                     :: "r"(mbar), "r"(WBYTES) : "memory");
    }
    __syncthreads();

    // ---- weights: 32 row copies (576 B) + 16 px1 replica copies (48 B) ----
    {
        unsigned sbase = (unsigned)__cvta_generic_to_shared(smem);
        if (t < 32) {
            int px = t >> 4, k = t & 15;
            unsigned d = sbase + (px ? (W0SZ + k * (W1STR * 4)) : (k * (W0STR * 4)));
            const float* src = weights + (size_t)(p0 + px) * (KN * CK) + k * CK;
            bulk_cp(d, src, CK * 4, mbar);
        } else if (t < 48) {
            int k = t - 32;                             // px1 cols 0..11 -> offset 144
            unsigned d = sbase + W0SZ + k * (W1STR * 4) + CK * 4;
            const float* src = weights + (size_t)(p0 + 1) * (KN * CK) + k * CK;
            bulk_cp(d, src, 48, mbar);
        }
    }

    // ---- gather (overlaps copies): 144 pair-tasks over 2 rounds (128 + 16) ----
    {
        #pragma unroll
        for (int r = 0; r < 2; r++) {
            int e = t + r * NT;
            if (r == 0 || t < (NPX * CK / 2 - NT)) {    // 128 + 16
                int px = e / (CK / 2);
                int c0 = (e - px * (CK / 2)) * 2;
                int elem = (p0 + px) * CK + c0;         // even -> aligned vec loads
                unsigned i0, i1;
                if (is64) {
                    uint4 v = __ldcs((const uint4*)&hidx32[2 * elem]);
                    i0 = v.x; i1 = v.z;
                } else {
                    uint2 v = __ldcs((const uint2*)&hidx32[elem]);
                    i0 = v.x; i1 = v.y;
                }
                uint4 h0 = __ldg((const uint4*)&g_xth[(size_t)(i0 & (IMG - 1)) * BB]);
                uint4 h1 = __ldg((const uint4*)&g_xth[(size_t)(i1 & (IMG - 1)) * BB]);
                float4 a0, b0, a1, b1;
                cvt8(h0, a0, b0);
                cvt8(h1, a1, b1);
                char* pb = patchb + px * P0B;
                *(float4*)(pb + c0 * 32)      = a0;
                *(float4*)(pb + c0 * 32 + 16) = b0;
                *(float4*)(pb + c0 * 32 + 32) = a1;
                *(float4*)(pb + c0 * 32 + 48) = b1;
                if (px == 1) {                          // replicas rows 144..152
                    if (c0 < 9) {
                        *(float4*)(pb + (CK + c0) * 32)      = a0;
                        *(float4*)(pb + (CK + c0) * 32 + 16) = b0;
                    }
                    if (c0 + 1 < 9) {
                        *(float4*)(pb + (CK + c0 + 1) * 32)      = a1;
                        *(float4*)(pb + (CK + c0 + 1) * 32 + 16) = b1;
                    }
                }
            }
        }
    }

    __syncthreads();          // patch visible

    // wait for weight copies
    asm volatile(
        "{\n\t"
        ".reg .pred P1;\n\t"
        "WL_%=:\n\t"
        "mbarrier.try_wait.parity.acquire.cta.shared::cta.b64 P1, [%0], 0, 0x989680;\n\t"
        "@P1 bra.uni WD_%=;\n\t"
        "bra.uni WL_%=;\n\t"
        "WD_%=:\n\t"
        "}\n"
        :: "r"(mbar) : "memory");

    // ---- compute: thread = (kp, cpx, s); k-rows (kp, kp+8); cb = 18s + 9cpx.
    //      No wraps, no cvts: all smem addresses pointer+immediate.
    const int kp  = t & 7;
    const int cpx = (t >> 3) & 1;
    const int s   = t >> 4;
    const int cb  = s * 18 + cpx * 9;
    float rr0[8], rr1[8];
    {
        const float* wr0 = cpx ? (smem + W0SZ / 4 + kp * W1STR)
                               : (smem + kp * W0STR);
        const float* wc0 = wr0 + cb;
        const float* wc1 = wc0 + 8 * (cpx ? W1STR : W0STR);
        const char*  pc  = patchb + cpx * P0B + cb * 32;
        unsigned long long a0[4] = {0ull,0ull,0ull,0ull};
        unsigned long long a1[4] = {0ull,0ull,0ull,0ull};
        #pragma unroll
        for (int j = 0; j < 18; j++) {
            ulonglong2 pA = *(const ulonglong2*)(pc + j * 32);        // b0..3
            ulonglong2 pB = *(const ulonglong2*)(pc + j * 32 + 16);   // b4..7
            float w0 = wc0[j];
            float w1 = wc1[j];
            unsigned long long W0, W1;
            asm("mov.b64 %0, {%1, %1};" : "=l"(W0) : "f"(w0));
            asm("mov.b64 %0, {%1, %1};" : "=l"(W1) : "f"(w1));
            fma2(a0[0], W0, pA.x); fma2(a0[1], W0, pA.y);
            fma2(a0[2], W0, pB.x); fma2(a0[3], W0, pB.y);
            fma2(a1[0], W1, pA.x); fma2(a1[1], W1, pA.y);
            fma2(a1[2], W1, pB.x); fma2(a1[3], W1, pB.y);
        }
        #pragma unroll
        for (int q = 0; q < 4; q++) {
            rr0[2 * q]     = __uint_as_float((unsigned)a0[q]);
            rr0[2 * q + 1] = __uint_as_float((unsigned)(a0[q] >> 32));
            rr1[2 * q]     = __uint_as_float((unsigned)a1[q]);
            rr1[2 * q + 1] = __uint_as_float((unsigned)(a1[q] >> 32));
        }
    }
    // reduce s-parity (lane bit 4)
    #pragma unroll
    for (int b = 0; b < 8; b++) {
        rr0[b] += __shfl_xor_sync(0xFFFFFFFFu, rr0[b], 16);
        rr1[b] += __shfl_xor_sync(0xFFFFFFFFu, rr1[b], 16);
    }

    // ---- stage warp-partials (overlay patch): [wg][cpx][b][kp*2+half] ----
    __syncthreads();                        // all smem reads done
    float* outsm = (float*)patchb;          // 1024 floats
    if ((t & 16) == 0) {
        const int wg = t >> 5;
        float* dst = outsm + ((wg * 2 + cpx) * 8) * KN + kp * 2;
        #pragma unroll
        for (int b = 0; b < 8; b++)
            *(float2*)&dst[b * KN] = make_float2(rr0[b], rr1[b]);
    }
    __syncthreads();

    {
        const int k = t & 15, b = t >> 4;
        const int ki = (k & 7) * 2 + (k >> 3);
        float s0 = 0.f, s1 = 0.f;
        #pragma unroll
        for (int wg = 0; wg < 4; wg++) {
            s0 += outsm[((wg * 2 + 0) * 8 + b) * KN + ki];
            s1 += outsm[((wg * 2 + 1) * 8 + b) * KN + ki];
        }
        __stcs((float2*)&out[(((size_t)b * KN + k) << 14) + p0], make_float2(s0, s1));
    }
}

extern "C" void kernel_launch(void* const* d_in, const int* in_sizes, int n_in,
                              void* d_out, int out_size) {
    const float*    x   = (const float*)d_in[0];
    const float*    w   = (const float*)d_in[1];
    const unsigned* hid = (const unsigned*)d_in[2];
    float*          out = (float*)d_out;
    (void)in_sizes; (void)n_in; (void)out_size;

    cudaFuncSetAttribute(abc2d_kernel,
                         cudaFuncAttributeMaxDynamicSharedMemorySize, SMEM_BYTES);
    transpose_kernel<<<IMG / 256, 256>>>(x, hid);
    abc2d_kernel<<<PP / NPX, NT, SMEM_BYTES>>>(w, hid, out);
}